// round 5
// baseline (speedup 1.0000x reference)
#include <cuda_runtime.h>
#include <cstdint>

#define NTT    128
#define NZZ    256
#define NNODE  32768
#define BB     16
#define HH     64
#define MTOT   524288      /* BB*NNODE rows */
#define NBLK1  4096        /* MTOT/128 gemm blocks */

#define LDA1 132
#define LDA2 68
#define LDB  72

// ---------------- scratch (device globals: allocation-free) ----------------
__device__ __align__(16) float g_hA[(size_t)MTOT * HH];     // h double-buffer A
__device__ __align__(16) float g_hB[(size_t)MTOT * HH];     // h double-buffer B
__device__ __align__(16) float g_y1[(size_t)MTOT * HH];     // gemm1 output (pre-BN1)
__device__ __align__(16) float g_y2[(size_t)MTOT * HH];     // gemm2 output (pre-BN2)
__device__ __align__(16) float g_statsP[128 * NBLK1];       // [c(sum|sq)][block]
__device__ __align__(16) float g_ss[256];                   // slot0: bn1 sc|sh, slot1: bn2 sc|sh
__device__ __align__(16) float g_poolP[BB * 32 * 64];       // pooling partials

// ---------------- helpers ----------------
__device__ __forceinline__ float tf32f(float x) {
    uint32_t u;
    asm("cvt.rna.tf32.f32 %0, %1;" : "=r"(u) : "f"(x));
    return __uint_as_float(u);
}

__device__ __forceinline__ void mma8(float* c, uint32_t a0, uint32_t a1, uint32_t a2,
                                     uint32_t a3, uint32_t b0, uint32_t b1) {
    asm volatile(
        "mma.sync.aligned.m16n8k8.row.col.f32.tf32.tf32.f32 "
        "{%0,%1,%2,%3},{%4,%5,%6,%7},{%8,%9},{%0,%1,%2,%3};"
        : "+f"(c[0]), "+f"(c[1]), "+f"(c[2]), "+f"(c[3])
        : "r"(a0), "r"(a1), "r"(a2), "r"(a3), "r"(b0), "r"(b1));
}

#define RESID4(v, yv, sc, sh)                                   \
    v.x += fmaxf(fmaf(yv.x, sc.x, sh.x), 0.f);                  \
    v.y += fmaxf(fmaf(yv.y, sc.y, sh.y), 0.f);                  \
    v.z += fmaxf(fmaf(yv.z, sc.z, sh.z), 0.f);                  \
    v.w += fmaxf(fmaf(yv.w, sc.w, sh.w), 0.f);

// ---------------- embed: h = relu(x^T @ W + b) ----------------
__global__ void embed_k(const float* __restrict__ x, const float* __restrict__ W,
                        const float* __restrict__ bias) {
    int i4 = blockIdx.x * 256 + threadIdx.x;          // float4 index over (b,n,ch)
    int c4 = i4 & 15;
    int n  = (i4 >> 4) & (NNODE - 1);
    int b  = i4 >> 19;
    const float* xb = x + (size_t)b * 3 * NNODE + n;
    float x0 = __ldg(xb), x1 = __ldg(xb + NNODE), x2 = __ldg(xb + 2 * NNODE);
    float4 w0 = __ldg((const float4*)W + c4);
    float4 w1 = __ldg((const float4*)W + 16 + c4);
    float4 w2 = __ldg((const float4*)W + 32 + c4);
    float4 bv = __ldg((const float4*)bias + c4);
    float4 o;
    o.x = fmaxf(fmaf(x2, w2.x, fmaf(x1, w1.x, fmaf(x0, w0.x, bv.x))), 0.f);
    o.y = fmaxf(fmaf(x2, w2.y, fmaf(x1, w1.y, fmaf(x0, w0.y, bv.y))), 0.f);
    o.z = fmaxf(fmaf(x2, w2.z, fmaf(x1, w1.z, fmaf(x0, w0.z, bv.z))), 0.f);
    o.w = fmaxf(fmaf(x2, w2.w, fmaf(x1, w1.w, fmaf(x0, w0.w, bv.w))), 0.f);
    ((float4*)g_hA)[i4] = o;
}

// ============================================================================
// Shared epilogue: direct STG from accumulators + register stats via shfl.
// ============================================================================
__device__ __forceinline__ void epilogue(float acc[4][4], float* sA, float* yout,
                                         int r0, int rg, int cg, int g, int tg,
                                         int tid, int bid) {
    {
        float* yo = yout + (size_t)(r0 + rg * 16 + g) * HH + cg * 32 + 2 * tg;
#pragma unroll
        for (int nt = 0; nt < 4; nt++) {
            *(float2*)(yo + nt * 8)            = make_float2(acc[nt][0], acc[nt][1]);
            *(float2*)(yo + 8 * HH + nt * 8)   = make_float2(acc[nt][2], acc[nt][3]);
        }
    }
    float cs[8], cq[8];
#pragma unroll
    for (int nt = 0; nt < 4; nt++) {
        cs[2 * nt]     = acc[nt][0] + acc[nt][2];
        cs[2 * nt + 1] = acc[nt][1] + acc[nt][3];
        cq[2 * nt]     = acc[nt][0] * acc[nt][0] + acc[nt][2] * acc[nt][2];
        cq[2 * nt + 1] = acc[nt][1] * acc[nt][1] + acc[nt][3] * acc[nt][3];
    }
#pragma unroll
    for (int off = 4; off <= 16; off <<= 1) {
#pragma unroll
        for (int i = 0; i < 8; i++) {
            cs[i] += __shfl_xor_sync(0xffffffffu, cs[i], off);
            cq[i] += __shfl_xor_sync(0xffffffffu, cq[i], off);
        }
    }
    __syncthreads();
    float* sS = sA;
    float* sQ = sA + 512;
    if (g == 0) {
#pragma unroll
        for (int nt = 0; nt < 4; nt++) {
            int col = cg * 32 + nt * 8 + 2 * tg;
            sS[rg * 64 + col]     = cs[2 * nt];
            sS[rg * 64 + col + 1] = cs[2 * nt + 1];
            sQ[rg * 64 + col]     = cq[2 * nt];
            sQ[rg * 64 + col + 1] = cq[2 * nt + 1];
        }
    }
    __syncthreads();
    if (tid < 128) {
        int c = tid & 63;
        const float* base = (tid < 64) ? sS : sQ;
        float v = 0.f;
#pragma unroll
        for (int w8 = 0; w8 < 8; w8++) v += base[w8 * 64 + c];
        g_statsP[(size_t)tid * NBLK1 + bid] = v;
    }
}

// ---------------- GEMM1: y1 = [h' | stencil(h')/4] @ W1, + channel stats ------
// FUSE: h' = h + relu(bn2(y2)) computed in registers at all 5 stencil positions;
//       center h' also written to the other h buffer (double-buffered).
template <bool FUSE>
__global__ void __launch_bounds__(512, 2) gemm1_t(const float* __restrict__ W, int hswap) {
    extern __shared__ float sm[];
    float* sA = sm;                 // 128 x LDA1 (tf32: [h(64)|agg(64)])
    float* sW = sm + 128 * LDA1;    // 128 x LDB  (tf32 weights)
    int tid = threadIdx.x;
    int r0 = blockIdx.x << 7;
    int b  = r0 >> 15;
    int n0 = r0 & (NNODE - 1);
    int t  = n0 >> 8;
    int z0 = n0 & 255;
    size_t boff = (size_t)b * NNODE * HH;
    const float* hb = ((FUSE && hswap) ? g_hB : g_hA) + boff;
    const float* yb = g_y2 + boff;
    float* ho = (hswap ? g_hA : g_hB) + boff;
    {
        int row = tid >> 2, ch0 = (tid & 3) << 4;
        int z = z0 + row;
        int iC  = ((t << 8) + z) * HH + ch0;
        int izm = ((t << 8) + ((z - 1) & 255)) * HH + ch0;
        int izp = ((t << 8) + ((z + 1) & 255)) * HH + ch0;
        int itm = ((((t - 1) & 127) << 8) + z) * HH + ch0;
        int itp = ((((t + 1) & 127) << 8) + z) * HH + ch0;
        float* aC = sA + row * LDA1 + ch0;
        const float4* scv = (const float4*)(g_ss + 128) + (ch0 >> 2);
        const float4* shv = (const float4*)(g_ss + 192) + (ch0 >> 2);
#pragma unroll
        for (int i = 0; i < 4; i++) {
            float4 c = __ldg((const float4*)(hb + iC) + i);
            float4 p = __ldg((const float4*)(hb + izm) + i);
            float4 q = __ldg((const float4*)(hb + izp) + i);
            float4 r = __ldg((const float4*)(hb + itm) + i);
            float4 s = __ldg((const float4*)(hb + itp) + i);
            if (FUSE) {
                float4 sc = __ldg(scv + i);
                float4 sh = __ldg(shv + i);
                float4 yc = __ldg((const float4*)(yb + iC) + i);
                float4 yp = __ldg((const float4*)(yb + izm) + i);
                float4 yq = __ldg((const float4*)(yb + izp) + i);
                float4 yr = __ldg((const float4*)(yb + itm) + i);
                float4 ys = __ldg((const float4*)(yb + itp) + i);
                RESID4(c, yc, sc, sh);
                RESID4(p, yp, sc, sh);
                RESID4(q, yq, sc, sh);
                RESID4(r, yr, sc, sh);
                RESID4(s, ys, sc, sh);
                ((float4*)(ho + iC))[i] = c;     // materialize h' (center)
            }
            float4 o;
            o.x = tf32f(c.x); o.y = tf32f(c.y); o.z = tf32f(c.z); o.w = tf32f(c.w);
            ((float4*)aC)[i] = o;
            float4 a;
            a.x = tf32f((p.x + q.x + r.x + s.x) * 0.25f);
            a.y = tf32f((p.y + q.y + r.y + s.y) * 0.25f);
            a.z = tf32f((p.z + q.z + r.z + s.z) * 0.25f);
            a.w = tf32f((p.w + q.w + r.w + s.w) * 0.25f);
            ((float4*)(aC + 64))[i] = a;
        }
#pragma unroll
        for (int i = 0; i < 16; i++) {
            int idx = tid + (i << 9);
            sW[(idx >> 6) * LDB + (idx & 63)] = tf32f(__ldg(W + idx));
        }
    }
    __syncthreads();

    int lane = tid & 31, w = tid >> 5;
    int rg = w & 7, cg = w >> 3;
    int g = lane >> 2, tg = lane & 3;
    float acc[4][4];
#pragma unroll
    for (int i = 0; i < 4; i++)
#pragma unroll
        for (int j = 0; j < 4; j++) acc[i][j] = 0.f;
    const float* A0 = sA + (rg * 16 + g) * LDA1;
#pragma unroll
    for (int ks = 0; ks < 16; ks++) {
        int kb = ks << 3;
        uint32_t a0 = __float_as_uint(A0[kb + tg]);
        uint32_t a1 = __float_as_uint(A0[8 * LDA1 + kb + tg]);
        uint32_t a2 = __float_as_uint(A0[kb + tg + 4]);
        uint32_t a3 = __float_as_uint(A0[8 * LDA1 + kb + tg + 4]);
        const float* B0 = sW + (kb + tg) * LDB + cg * 32 + g;
#pragma unroll
        for (int nt = 0; nt < 4; nt++) {
            uint32_t b0 = __float_as_uint(B0[nt * 8]);
            uint32_t b1 = __float_as_uint(B0[4 * LDB + nt * 8]);
            mma8(acc[nt], a0, a1, a2, a3, b0, b1);
        }
    }
    epilogue(acc, sA, g_y1, r0, rg, cg, g, tg, tid, blockIdx.x);
}

// ---------------- GEMM2: y2 = relu(bn1(y1)) @ W2, + channel stats ------------
__global__ void __launch_bounds__(512, 2) gemm2_k(const float* __restrict__ W) {
    extern __shared__ float sm[];
    float* sA = sm;                 // 128 x LDA2
    float* sW = sm + 128 * LDA2;    // 64 x LDB
    int tid = threadIdx.x;
    int r0 = blockIdx.x << 7;
    {
        int row = tid >> 2, ch0 = (tid & 3) << 4;
        const float4* yi = (const float4*)(g_y1 + ((size_t)(r0 + row)) * HH + ch0);
        const float4* scv = (const float4*)g_ss + (ch0 >> 2);
        const float4* shv = (const float4*)(g_ss + 64) + (ch0 >> 2);
        float* aC = sA + row * LDA2 + ch0;
#pragma unroll
        for (int i = 0; i < 4; i++) {
            float4 v = __ldg(yi + i);
            float4 sc = __ldg(scv + i);
            float4 sh = __ldg(shv + i);
            float4 o;
            o.x = tf32f(fmaxf(fmaf(v.x, sc.x, sh.x), 0.f));
            o.y = tf32f(fmaxf(fmaf(v.y, sc.y, sh.y), 0.f));
            o.z = tf32f(fmaxf(fmaf(v.z, sc.z, sh.z), 0.f));
            o.w = tf32f(fmaxf(fmaf(v.w, sc.w, sh.w), 0.f));
            ((float4*)aC)[i] = o;
        }
#pragma unroll
        for (int i = 0; i < 8; i++) {
            int idx = tid + (i << 9);
            sW[(idx >> 6) * LDB + (idx & 63)] = tf32f(__ldg(W + idx));
        }
    }
    __syncthreads();

    int lane = tid & 31, w = tid >> 5;
    int rg = w & 7, cg = w >> 3;
    int g = lane >> 2, tg = lane & 3;
    float acc[4][4];
#pragma unroll
    for (int i = 0; i < 4; i++)
#pragma unroll
        for (int j = 0; j < 4; j++) acc[i][j] = 0.f;
    const float* A0 = sA + (rg * 16 + g) * LDA2;
#pragma unroll
    for (int ks = 0; ks < 8; ks++) {
        int kb = ks << 3;
        uint32_t a0 = __float_as_uint(A0[kb + tg]);
        uint32_t a1 = __float_as_uint(A0[8 * LDA2 + kb + tg]);
        uint32_t a2 = __float_as_uint(A0[kb + tg + 4]);
        uint32_t a3 = __float_as_uint(A0[8 * LDA2 + kb + tg + 4]);
        const float* B0 = sW + (kb + tg) * LDB + cg * 32 + g;
#pragma unroll
        for (int nt = 0; nt < 4; nt++) {
            uint32_t b0 = __float_as_uint(B0[nt * 8]);
            uint32_t b1 = __float_as_uint(B0[4 * LDB + nt * 8]);
            mma8(acc[nt], a0, a1, a2, a3, b0, b1);
        }
    }
    epilogue(acc, sA, g_y2, r0, rg, cg, g, tg, tid, blockIdx.x);
}

// ---------------- stats finalize: scale/shift per channel (fp64) -------------
__global__ void finalize_k(const float* __restrict__ gma, const float* __restrict__ be,
                           int slot) {
    int c = blockIdx.x, tid = threadIdx.x;
    double s = 0.0, s2 = 0.0;
    for (int k = tid; k < NBLK1; k += 256) {
        s  += (double)g_statsP[(size_t)c * NBLK1 + k];
        s2 += (double)g_statsP[(size_t)(64 + c) * NBLK1 + k];
    }
    __shared__ double shs[256], shq[256];
    shs[tid] = s; shq[tid] = s2;
    __syncthreads();
    for (int st = 128; st; st >>= 1) {
        if (tid < st) { shs[tid] += shs[tid + st]; shq[tid] += shq[tid + st]; }
        __syncthreads();
    }
    if (tid == 0) {
        double mean = shs[0] / (double)MTOT;
        double var  = shq[0] / (double)MTOT - mean * mean;
        float sc = (float)((double)__ldg(gma + c) / sqrt(var + 1e-5));
        g_ss[slot * 128 + c]      = sc;
        g_ss[slot * 128 + 64 + c] = __ldg(be + c) - (float)mean * sc;
    }
}

// ---------------- pooling partials (fused final residual) --------------------
// h_final = h2 + relu(bn2(y2_2));  h2 lives in g_hA (layer-2 gemm1 wrote it).
__global__ void pool_k() {
    int b = blockIdx.y, chunk = blockIdx.x;
    int c = threadIdx.x, r = threadIdx.y;
    size_t base = ((size_t)b * NNODE + (chunk << 10)) * HH;
    const float* hb = g_hA + base;
    const float* yb = g_y2 + base;
    float sc = g_ss[128 + c], sh = g_ss[192 + c];
    float s = 0.f;
#pragma unroll 8
    for (int i = 0; i < 256; i++) {
        int off = ((i << 2) + r) * HH + c;
        s += hb[off] + fmaxf(fmaf(yb[off], sc, sh), 0.f);
    }
    __shared__ float sb[4][64];
    sb[r][c] = s;
    __syncthreads();
    if (r == 0) g_poolP[((b << 5) + chunk) * 64 + c] = sb[0][c] + sb[1][c] + sb[2][c] + sb[3][c];
}

// ---------------- head: out = relu(pooled@W1+b1)@W2+b2 ----------------
__global__ void head_k(const float* __restrict__ W1, const float* __restrict__ b1,
                       const float* __restrict__ W2, const float* __restrict__ b2,
                       float* __restrict__ out) {
    __shared__ float pooled[16 * 64], z1[16 * 64];
    int tid = threadIdx.x;
    for (int i = tid; i < 1024; i += 256) {
        int bb = i >> 6, c = i & 63;
        float s = 0.f;
        const float* pp = g_poolP + (bb << 5) * 64 + c;
#pragma unroll 8
        for (int k = 0; k < 32; k++) s += pp[k * 64];
        pooled[i] = s * (1.0f / NNODE);
    }
    __syncthreads();
    for (int i = tid; i < 1024; i += 256) {
        int bb = i >> 6, j = i & 63;
        float s = __ldg(b1 + j);
        const float* pv = pooled + (bb << 6);
#pragma unroll 8
        for (int c2 = 0; c2 < 64; c2++) s = fmaf(pv[c2], __ldg(W1 + c2 * 64 + j), s);
        z1[i] = fmaxf(s, 0.f);
    }
    __syncthreads();
    for (int i = tid; i < 2048; i += 256) {
        int bb = i >> 7, d = i & 127;
        float s = __ldg(b2 + d);
        const float* zv = z1 + (bb << 6);
#pragma unroll 8
        for (int j = 0; j < 64; j++) s = fmaf(zv[j], __ldg(W2 + j * 128 + d), s);
        out[(bb << 7) + d] = s;
    }
}

// ---------------- launch ----------------
extern "C" void kernel_launch(void* const* d_in, const int* in_sizes, int n_in,
                              void* d_out, int out_size) {
    (void)in_sizes; (void)n_in; (void)out_size;
    const float* x    = (const float*)d_in[0];
    // d_in[1] edge_index: fixed torus stencil, computed analytically
    const float* embW = (const float*)d_in[2];
    const float* embB = (const float*)d_in[3];
    const float* W1   = (const float*)d_in[4];
    // d_in[5] mp_b1: cancels through BatchNorm exactly
    const float* g1   = (const float*)d_in[6];
    const float* be1  = (const float*)d_in[7];
    const float* W2   = (const float*)d_in[8];
    // d_in[9] mp_b2: cancels through BatchNorm exactly
    const float* g2   = (const float*)d_in[10];
    const float* be2  = (const float*)d_in[11];
    const float* hW1  = (const float*)d_in[12];
    const float* hb1  = (const float*)d_in[13];
    const float* hW2  = (const float*)d_in[14];
    const float* hb2  = (const float*)d_in[15];
    float* out = (float*)d_out;

    cudaFuncSetAttribute(gemm1_t<false>, cudaFuncAttributeMaxDynamicSharedMemorySize, 104448);
    cudaFuncSetAttribute(gemm1_t<true>,  cudaFuncAttributeMaxDynamicSharedMemorySize, 104448);
    cudaFuncSetAttribute(gemm2_k, cudaFuncAttributeMaxDynamicSharedMemorySize, 53248);

    embed_k<<<32768, 256>>>(x, embW, embB);

    // layer 0: plain gemm1 (h0 in g_hA)
    gemm1_t<false><<<NBLK1, 512, 104448>>>(W1, 0);
    finalize_k<<<64, 256>>>(g1, be1, 0);
    gemm2_k<<<NBLK1, 512, 53248>>>(W2);
    finalize_k<<<64, 256>>>(g2, be2, 1);

    // layer 1: fused residual (h0=g_hA, y2_0=g_y2 -> h1 into g_hB)
    gemm1_t<true><<<NBLK1, 512, 104448>>>(W1 + 8192, 0);
    finalize_k<<<64, 256>>>(g1 + 64, be1 + 64, 0);
    gemm2_k<<<NBLK1, 512, 53248>>>(W2 + 4096);
    finalize_k<<<64, 256>>>(g2 + 64, be2 + 64, 1);

    // layer 2: fused residual (h1=g_hB -> h2 into g_hA)
    gemm1_t<true><<<NBLK1, 512, 104448>>>(W1 + 16384, 1);
    finalize_k<<<64, 256>>>(g1 + 128, be1 + 128, 0);
    gemm2_k<<<NBLK1, 512, 53248>>>(W2 + 8192);
    finalize_k<<<64, 256>>>(g2 + 128, be2 + 128, 1);

    // pool fuses the final residual: h_final = h2 + relu(bn2(y2_2))
    pool_k<<<dim3(32, 16), dim3(64, 4)>>>();
    head_k<<<1, 256>>>(hW1, hb1, hW2, hb2, out);
}

// round 7
// speedup vs baseline: 2.1228x; 2.1228x over previous
#include <cuda_runtime.h>
#include <cuda_bf16.h>
#include <cstdint>

#define NTT    128
#define NZZ    256
#define NNODE  32768
#define BB     16
#define HH     64
#define MTOT   524288      /* BB*NNODE rows */
#define NBLK1  4096        /* MTOT/128 gemm blocks */

#define LDA1W 68           /* words (bf16 pairs) per A row, gemm1 (64 + pad) */
#define LDB1W 68           /* words per B row, gemm1 */
#define LDA2W 36           /* gemm2: 32 + pad */
#define LDB2W 36

// ---------------- scratch (device globals: allocation-free) ----------------
__device__ __align__(16) __nv_bfloat16 g_h[(size_t)MTOT * HH];   // 64 MB residual stream
__device__ __align__(16) __nv_bfloat16 g_y[(size_t)MTOT * HH];   // 64 MB activations
__device__ __align__(16) float g_statsP[128 * NBLK1];            // [c(sum|sq)][block]
__device__ __align__(16) float g_ss[256];                        // slot0 bn1 sc|sh, slot1 bn2
__device__ __align__(16) float g_poolP[BB * 32 * 64];            // pooling partials

// ---------------- helpers ----------------
__device__ __forceinline__ uint32_t packbf(float a, float b) {
    __nv_bfloat162 t = __floats2bfloat162_rn(a, b);
    return *reinterpret_cast<uint32_t*>(&t);
}
__device__ __forceinline__ float2 upf(uint32_t u) {
    __nv_bfloat162 t = *reinterpret_cast<__nv_bfloat162*>(&u);
    return __bfloat1622float2(t);
}

__device__ __forceinline__ void mma16(float* c, uint32_t a0, uint32_t a1, uint32_t a2,
                                      uint32_t a3, uint32_t b0, uint32_t b1) {
    asm volatile(
        "mma.sync.aligned.m16n8k16.row.col.f32.bf16.bf16.f32 "
        "{%0,%1,%2,%3},{%4,%5,%6,%7},{%8,%9},{%0,%1,%2,%3};"
        : "+f"(c[0]), "+f"(c[1]), "+f"(c[2]), "+f"(c[3])
        : "r"(a0), "r"(a1), "r"(a2), "r"(a3), "r"(b0), "r"(b1));
}

// ---------------- embed: h = relu(x^T @ W + b)  (bf16 out) ----------------
__global__ void embed_k(const float* __restrict__ x, const float* __restrict__ W,
                        const float* __restrict__ bias) {
    int i8 = blockIdx.x * 256 + threadIdx.x;      // 8-channel group index
    int cg8 = i8 & 7;
    int n   = (i8 >> 3) & (NNODE - 1);
    int b   = i8 >> 18;
    const float* xb = x + (size_t)b * 3 * NNODE + n;
    float x0 = __ldg(xb), x1 = __ldg(xb + NNODE), x2 = __ldg(xb + 2 * NNODE);
    float wa[8], wb[8], wc[8], bv[8];
    const float4* W4 = (const float4*)W;
    *(float4*)&wa[0] = __ldg(W4 + cg8 * 2);      *(float4*)&wa[4] = __ldg(W4 + cg8 * 2 + 1);
    *(float4*)&wb[0] = __ldg(W4 + 16 + cg8 * 2); *(float4*)&wb[4] = __ldg(W4 + 16 + cg8 * 2 + 1);
    *(float4*)&wc[0] = __ldg(W4 + 32 + cg8 * 2); *(float4*)&wc[4] = __ldg(W4 + 32 + cg8 * 2 + 1);
    *(float4*)&bv[0] = __ldg((const float4*)bias + cg8 * 2);
    *(float4*)&bv[4] = __ldg((const float4*)bias + cg8 * 2 + 1);
    uint32_t ww[4];
#pragma unroll
    for (int j = 0; j < 4; j++) {
        float e0 = fmaxf(fmaf(x2, wc[2 * j],     fmaf(x1, wb[2 * j],     fmaf(x0, wa[2 * j],     bv[2 * j]))), 0.f);
        float e1 = fmaxf(fmaf(x2, wc[2 * j + 1], fmaf(x1, wb[2 * j + 1], fmaf(x0, wa[2 * j + 1], bv[2 * j + 1]))), 0.f);
        ww[j] = packbf(e0, e1);
    }
    ((uint4*)g_h)[i8] = *(uint4*)ww;
}

// ============================================================================
// Shared epilogue: bf16 STG from fp32 accumulators + register stats via shfl.
// ============================================================================
__device__ __forceinline__ void epilogue(float acc[4][4], float* sF,
                                         int r0, int rg, int cg, int g, int tg,
                                         int tid, int bid) {
    {
        __nv_bfloat16* yo = g_y + (size_t)(r0 + rg * 16 + g) * HH + cg * 32 + 2 * tg;
#pragma unroll
        for (int nt = 0; nt < 4; nt++) {
            *(uint32_t*)(yo + nt * 8)          = packbf(acc[nt][0], acc[nt][1]);
            *(uint32_t*)(yo + 8 * HH + nt * 8) = packbf(acc[nt][2], acc[nt][3]);
        }
    }
    float cs[8], cq[8];
#pragma unroll
    for (int nt = 0; nt < 4; nt++) {
        cs[2 * nt]     = acc[nt][0] + acc[nt][2];
        cs[2 * nt + 1] = acc[nt][1] + acc[nt][3];
        cq[2 * nt]     = acc[nt][0] * acc[nt][0] + acc[nt][2] * acc[nt][2];
        cq[2 * nt + 1] = acc[nt][1] * acc[nt][1] + acc[nt][3] * acc[nt][3];
    }
#pragma unroll
    for (int off = 4; off <= 16; off <<= 1) {
#pragma unroll
        for (int i = 0; i < 8; i++) {
            cs[i] += __shfl_xor_sync(0xffffffffu, cs[i], off);
            cq[i] += __shfl_xor_sync(0xffffffffu, cq[i], off);
        }
    }
    __syncthreads();
    float* sS = sF;
    float* sQ = sF + 512;
    if (g == 0) {
#pragma unroll
        for (int nt = 0; nt < 4; nt++) {
            int col = cg * 32 + nt * 8 + 2 * tg;
            sS[rg * 64 + col]     = cs[2 * nt];
            sS[rg * 64 + col + 1] = cs[2 * nt + 1];
            sQ[rg * 64 + col]     = cq[2 * nt];
            sQ[rg * 64 + col + 1] = cq[2 * nt + 1];
        }
    }
    __syncthreads();
    if (tid < 128) {
        int c = tid & 63;
        const float* base = (tid < 64) ? sS : sQ;
        float v = 0.f;
#pragma unroll
        for (int w8 = 0; w8 < 8; w8++) v += base[w8 * 64 + c];
        g_statsP[(size_t)tid * NBLK1 + bid] = v;
    }
}

// ---------------- GEMM1: y = [h | stencil(h)/4] @ W1, + channel stats --------
__global__ void __launch_bounds__(512, 2) gemm1_k(const float* __restrict__ W) {
    extern __shared__ uint32_t smw[];
    uint32_t* sA = smw;                  // 128 x LDA1W words ([h(32w)|agg(32w)])
    uint32_t* sB = smw + 128 * LDA1W;    // 64  x LDB1W words
    int tid = threadIdx.x;
    int r0 = blockIdx.x << 7;
    int b  = r0 >> 15;
    int n0 = r0 & (NNODE - 1);
    int t  = n0 >> 8;
    int z0 = n0 & 255;
    const __nv_bfloat16* hb = g_h + (size_t)b * NNODE * HH;
    {
        int row = tid >> 2, ch0 = (tid & 3) << 4;
        int z = z0 + row;
        int iC  = ((t << 8) + z) * HH;
        int izm = ((t << 8) + ((z - 1) & 255)) * HH;
        int izp = ((t << 8) + ((z + 1) & 255)) * HH;
        int itm = ((((t - 1) & 127) << 8) + z) * HH;
        int itp = ((((t + 1) & 127) << 8) + z) * HH;
        uint32_t* aw = sA + row * LDA1W + (ch0 >> 1);
#pragma unroll
        for (int i = 0; i < 2; i++) {
            int co = ch0 + i * 8;
            uint4 c = *(const uint4*)(hb + iC + co);
            uint4 p = *(const uint4*)(hb + izm + co);
            uint4 q = *(const uint4*)(hb + izp + co);
            uint4 r = *(const uint4*)(hb + itm + co);
            uint4 s = *(const uint4*)(hb + itp + co);
            *(uint4*)(aw + i * 4) = c;          // center: exact bf16 copy
            uint32_t ag[4];
#pragma unroll
            for (int j = 0; j < 4; j++) {
                float2 pp = upf(((uint32_t*)&p)[j]);
                float2 qq = upf(((uint32_t*)&q)[j]);
                float2 rr = upf(((uint32_t*)&r)[j]);
                float2 ss = upf(((uint32_t*)&s)[j]);
                ag[j] = packbf((pp.x + qq.x + rr.x + ss.x) * 0.25f,
                               (pp.y + qq.y + rr.y + ss.y) * 0.25f);
            }
            *(uint4*)(aw + 32 + i * 4) = *(uint4*)ag;
        }
        // weights: K=128, N=64 -> B[n][kw], kw packs (2kw, 2kw+1)
        int n = tid & 63, kq = tid >> 6;
#pragma unroll
        for (int i = 0; i < 8; i++) {
            int kw = kq * 8 + i;
            float lo = __ldg(W + (2 * kw) * 64 + n);
            float hi = __ldg(W + (2 * kw + 1) * 64 + n);
            sB[n * LDB1W + kw] = packbf(lo, hi);
        }
    }
    __syncthreads();

    int lane = tid & 31, w = tid >> 5;
    int rg = w & 7, cg = w >> 3;
    int g = lane >> 2, tg = lane & 3;
    float acc[4][4];
#pragma unroll
    for (int i = 0; i < 4; i++)
#pragma unroll
        for (int j = 0; j < 4; j++) acc[i][j] = 0.f;
    const uint32_t* A0 = sA + (rg * 16 + g) * LDA1W + tg;
    const uint32_t* B0 = sB + (cg * 32 + g) * LDB1W + tg;
#pragma unroll
    for (int ks = 0; ks < 8; ks++) {
        int kb = ks * 8;
        uint32_t a0 = A0[kb], a1 = A0[8 * LDA1W + kb];
        uint32_t a2 = A0[kb + 4], a3 = A0[8 * LDA1W + kb + 4];
#pragma unroll
        for (int nt = 0; nt < 4; nt++) {
            uint32_t b0 = B0[nt * 8 * LDB1W + kb];
            uint32_t b1 = B0[nt * 8 * LDB1W + kb + 4];
            mma16(acc[nt], a0, a1, a2, a3, b0, b1);
        }
    }
    epilogue(acc, (float*)sA, r0, rg, cg, g, tg, tid, blockIdx.x);
}

// ---------------- GEMM2: y = relu(bn1(y)) @ W2 (in place), + channel stats ---
__global__ void __launch_bounds__(512, 2) gemm2_k(const float* __restrict__ W) {
    extern __shared__ uint32_t smw[];
    uint32_t* sA = smw;                  // 128 x LDA2W
    uint32_t* sB = smw + 128 * LDA2W;    // 64  x LDB2W
    int tid = threadIdx.x;
    int r0 = blockIdx.x << 7;
    {
        int row = tid >> 2, ch0 = (tid & 3) << 4;
        const __nv_bfloat16* yb = g_y + (size_t)(r0 + row) * HH;
        uint32_t* aw = sA + row * LDA2W + (ch0 >> 1);
#pragma unroll
        for (int i = 0; i < 2; i++) {
            int co = ch0 + i * 8;
            uint4 v = *(const uint4*)(yb + co);
            uint32_t ow[4];
#pragma unroll
            for (int j = 0; j < 4; j++) {
                int ch = co + 2 * j;
                float2 f  = upf(((uint32_t*)&v)[j]);
                float2 sc = *(const float2*)(g_ss + ch);
                float2 sh = *(const float2*)(g_ss + 64 + ch);
                ow[j] = packbf(fmaxf(fmaf(f.x, sc.x, sh.x), 0.f),
                               fmaxf(fmaf(f.y, sc.y, sh.y), 0.f));
            }
            *(uint4*)(aw + i * 4) = *(uint4*)ow;
        }
        // weights: K=64, N=64
        int n = tid & 63, kq = tid >> 6;
#pragma unroll
        for (int i = 0; i < 4; i++) {
            int kw = kq * 4 + i;
            float lo = __ldg(W + (2 * kw) * 64 + n);
            float hi = __ldg(W + (2 * kw + 1) * 64 + n);
            sB[n * LDB2W + kw] = packbf(lo, hi);
        }
    }
    __syncthreads();

    int lane = tid & 31, w = tid >> 5;
    int rg = w & 7, cg = w >> 3;
    int g = lane >> 2, tg = lane & 3;
    float acc[4][4];
#pragma unroll
    for (int i = 0; i < 4; i++)
#pragma unroll
        for (int j = 0; j < 4; j++) acc[i][j] = 0.f;
    const uint32_t* A0 = sA + (rg * 16 + g) * LDA2W + tg;
    const uint32_t* B0 = sB + (cg * 32 + g) * LDB2W + tg;
#pragma unroll
    for (int ks = 0; ks < 4; ks++) {
        int kb = ks * 8;
        uint32_t a0 = A0[kb], a1 = A0[8 * LDA2W + kb];
        uint32_t a2 = A0[kb + 4], a3 = A0[8 * LDA2W + kb + 4];
#pragma unroll
        for (int nt = 0; nt < 4; nt++) {
            uint32_t b0 = B0[nt * 8 * LDB2W + kb];
            uint32_t b1 = B0[nt * 8 * LDB2W + kb + 4];
            mma16(acc[nt], a0, a1, a2, a3, b0, b1);
        }
    }
    epilogue(acc, (float*)sA, r0, rg, cg, g, tg, tid, blockIdx.x);
}

// ---------------- stats finalize: scale/shift per channel (fp64) -------------
__global__ void finalize_k(const float* __restrict__ gma, const float* __restrict__ be,
                           int slot) {
    int c = blockIdx.x, tid = threadIdx.x;
    double s = 0.0, s2 = 0.0;
    for (int k = tid; k < NBLK1; k += 256) {
        s  += (double)g_statsP[(size_t)c * NBLK1 + k];
        s2 += (double)g_statsP[(size_t)(64 + c) * NBLK1 + k];
    }
    __shared__ double shs[256], shq[256];
    shs[tid] = s; shq[tid] = s2;
    __syncthreads();
    for (int st = 128; st; st >>= 1) {
        if (tid < st) { shs[tid] += shs[tid + st]; shq[tid] += shq[tid + st]; }
        __syncthreads();
    }
    if (tid == 0) {
        double mean = shs[0] / (double)MTOT;
        double var  = shq[0] / (double)MTOT - mean * mean;
        float sc = (float)((double)__ldg(gma + c) / sqrt(var + 1e-5));
        g_ss[slot * 128 + c]      = sc;
        g_ss[slot * 128 + 64 + c] = __ldg(be + c) - (float)mean * sc;
    }
}

// ---------------- residual: h += relu(y*scale + shift)  (bf16) ---------------
__global__ void resid_k() {
    int base = blockIdx.x << 10;
#pragma unroll
    for (int j = 0; j < 4; j++) {
        int i8 = base + (j << 8) + threadIdx.x;
        int cg8 = i8 & 7;
        uint4 yv = ((const uint4*)g_y)[i8];
        uint4 hv = ((const uint4*)g_h)[i8];
        const float2* scp = (const float2*)(g_ss + 128) + cg8 * 4;
        const float2* shp = (const float2*)(g_ss + 192) + cg8 * 4;
        uint32_t ow[4];
#pragma unroll
        for (int k = 0; k < 4; k++) {
            float2 y2 = upf(((uint32_t*)&yv)[k]);
            float2 h2 = upf(((uint32_t*)&hv)[k]);
            float2 sc = scp[k], sh = shp[k];
            ow[k] = packbf(h2.x + fmaxf(fmaf(y2.x, sc.x, sh.x), 0.f),
                           h2.y + fmaxf(fmaf(y2.y, sc.y, sh.y), 0.f));
        }
        ((uint4*)g_h)[i8] = *(uint4*)ow;
    }
}

// ---------------- pooling partials over nodes (bf16 in, fp32 out) ------------
__global__ void pool_k() {     // grid (32,16), block (32,8)
    int b = blockIdx.y, chunk = blockIdx.x;
    int c2 = threadIdx.x, r = threadIdx.y;
    const __nv_bfloat16* hb = g_h + ((size_t)b * NNODE + (chunk << 10)) * HH;
    float s0 = 0.f, s1 = 0.f;
#pragma unroll 8
    for (int i = 0; i < 128; i++) {
        int off = ((i << 3) + r) * HH + c2 * 2;
        float2 f = upf(*(const uint32_t*)(hb + off));
        s0 += f.x; s1 += f.y;
    }
    __shared__ float sb[8][64];
    sb[r][c2 * 2] = s0; sb[r][c2 * 2 + 1] = s1;
    __syncthreads();
    int tid = r * 32 + c2;
    if (tid < 64) {
        float v = 0.f;
#pragma unroll
        for (int k = 0; k < 8; k++) v += sb[k][tid];
        g_poolP[((b << 5) + chunk) * 64 + tid] = v;
    }
}

// ---------------- head: out = relu(pooled@W1+b1)@W2+b2 (fp32 exact) ----------
__global__ void head_k(const float* __restrict__ W1, const float* __restrict__ b1,
                       const float* __restrict__ W2, const float* __restrict__ b2,
                       float* __restrict__ out) {
    __shared__ float pooled[16 * 64], z1[16 * 64];
    int tid = threadIdx.x;
    for (int i = tid; i < 1024; i += 256) {
        int bb = i >> 6, c = i & 63;
        float s = 0.f;
        const float* pp = g_poolP + (bb << 5) * 64 + c;
#pragma unroll 8
        for (int k = 0; k < 32; k++) s += pp[k * 64];
        pooled[i] = s * (1.0f / NNODE);
    }
    __syncthreads();
    for (int i = tid; i < 1024; i += 256) {
        int bb = i >> 6, j = i & 63;
        float s = __ldg(b1 + j);
        const float* pv = pooled + (bb << 6);
#pragma unroll 8
        for (int c2 = 0; c2 < 64; c2++) s = fmaf(pv[c2], __ldg(W1 + c2 * 64 + j), s);
        z1[i] = fmaxf(s, 0.f);
    }
    __syncthreads();
    for (int i = tid; i < 2048; i += 256) {
        int bb = i >> 7, d = i & 127;
        float s = __ldg(b2 + d);
        const float* zv = z1 + (bb << 6);
#pragma unroll 8
        for (int j = 0; j < 64; j++) s = fmaf(zv[j], __ldg(W2 + j * 128 + d), s);
        out[(bb << 7) + d] = s;
    }
}

// ---------------- launch ----------------
extern "C" void kernel_launch(void* const* d_in, const int* in_sizes, int n_in,
                              void* d_out, int out_size) {
    (void)in_sizes; (void)n_in; (void)out_size;
    const float* x    = (const float*)d_in[0];
    // d_in[1] edge_index: fixed torus stencil, computed analytically
    const float* embW = (const float*)d_in[2];
    const float* embB = (const float*)d_in[3];
    const float* W1   = (const float*)d_in[4];
    // d_in[5] mp_b1: cancels through BatchNorm exactly
    const float* g1   = (const float*)d_in[6];
    const float* be1  = (const float*)d_in[7];
    const float* W2   = (const float*)d_in[8];
    // d_in[9] mp_b2: cancels through BatchNorm exactly
    const float* g2   = (const float*)d_in[10];
    const float* be2  = (const float*)d_in[11];
    const float* hW1  = (const float*)d_in[12];
    const float* hb1  = (const float*)d_in[13];
    const float* hW2  = (const float*)d_in[14];
    const float* hb2  = (const float*)d_in[15];
    float* out = (float*)d_out;

    const int SM1 = (128 * LDA1W + 64 * LDB1W) * 4;   // 52224 B
    const int SM2 = (128 * LDA2W + 64 * LDB2W) * 4;   // 27648 B
    cudaFuncSetAttribute(gemm1_k, cudaFuncAttributeMaxDynamicSharedMemorySize, SM1);
    cudaFuncSetAttribute(gemm2_k, cudaFuncAttributeMaxDynamicSharedMemorySize, SM2);

    embed_k<<<16384, 256>>>(x, embW, embB);
    for (int l = 0; l < 3; l++) {
        gemm1_k<<<NBLK1, 512, SM1>>>(W1 + l * 8192);
        finalize_k<<<64, 256>>>(g1 + l * 64, be1 + l * 64, 0);
        gemm2_k<<<NBLK1, 512, SM2>>>(W2 + l * 4096);
        finalize_k<<<64, 256>>>(g2 + l * 64, be2 + l * 64, 1);
        resid_k<<<4096, 256>>>();
    }
    pool_k<<<dim3(32, 16), dim3(32, 8)>>>();
    head_k<<<1, 256>>>(hW1, hb1, hW2, hb2, out);
}

// round 8
// speedup vs baseline: 2.1509x; 1.0133x over previous
#include <cuda_runtime.h>
#include <cuda_bf16.h>
#include <cstdint>

#define NTT    128
#define NZZ    256
#define NNODE  32768
#define BB     16
#define HH     64
#define MTOT   524288      /* BB*NNODE rows */
#define NBLK1  4096        /* MTOT/128 gemm blocks */

#define LDA1W 68           /* words (bf16 pairs) per A row, gemm1 (64 + pad) */
#define LDB1W 68           /* words per B row, gemm1 */
#define LDA2W 36           /* gemm2: 32 + pad */
#define LDB2W 36

// ---------------- scratch (device globals: allocation-free) ----------------
__device__ __align__(16) __nv_bfloat16 g_h[(size_t)MTOT * HH];   // 64 MB residual stream
__device__ __align__(16) __nv_bfloat16 g_y[(size_t)MTOT * HH];   // 64 MB activations
__device__ __align__(16) float g_statsP[128 * NBLK1];            // [c(sum|sq)][block]
__device__ __align__(16) float g_ss[256];                        // slot0 bn1 sc|sh, slot1 bn2
__device__ __align__(16) float g_poolP[BB * 32 * 64];            // pooling partials

// ---------------- helpers ----------------
__device__ __forceinline__ uint32_t packbf(float a, float b) {
    __nv_bfloat162 t = __floats2bfloat162_rn(a, b);
    return *reinterpret_cast<uint32_t*>(&t);
}
__device__ __forceinline__ float2 upf(uint32_t u) {
    __nv_bfloat162 t = *reinterpret_cast<__nv_bfloat162*>(&u);
    return __bfloat1622float2(t);
}

__device__ __forceinline__ void mma16(float* c, uint32_t a0, uint32_t a1, uint32_t a2,
                                      uint32_t a3, uint32_t b0, uint32_t b1) {
    asm volatile(
        "mma.sync.aligned.m16n8k16.row.col.f32.bf16.bf16.f32 "
        "{%0,%1,%2,%3},{%4,%5,%6,%7},{%8,%9},{%0,%1,%2,%3};"
        : "+f"(c[0]), "+f"(c[1]), "+f"(c[2]), "+f"(c[3])
        : "r"(a0), "r"(a1), "r"(a2), "r"(a3), "r"(b0), "r"(b1));
}

__device__ __forceinline__ void ldsm4(uint32_t& r0, uint32_t& r1, uint32_t& r2,
                                      uint32_t& r3, uint32_t addr) {
    asm volatile("ldmatrix.sync.aligned.m8n8.x4.shared.b16 {%0,%1,%2,%3}, [%4];"
                 : "=r"(r0), "=r"(r1), "=r"(r2), "=r"(r3) : "r"(addr));
}

// ---------------- embed: h = relu(x^T @ W + b)  (bf16 out) ----------------
__global__ void embed_k(const float* __restrict__ x, const float* __restrict__ W,
                        const float* __restrict__ bias) {
    int i8 = blockIdx.x * 256 + threadIdx.x;      // 8-channel group index
    int cg8 = i8 & 7;
    int n   = (i8 >> 3) & (NNODE - 1);
    int b   = i8 >> 18;
    const float* xb = x + (size_t)b * 3 * NNODE + n;
    float x0 = __ldg(xb), x1 = __ldg(xb + NNODE), x2 = __ldg(xb + 2 * NNODE);
    float wa[8], wb[8], wc[8], bv[8];
    const float4* W4 = (const float4*)W;
    *(float4*)&wa[0] = __ldg(W4 + cg8 * 2);      *(float4*)&wa[4] = __ldg(W4 + cg8 * 2 + 1);
    *(float4*)&wb[0] = __ldg(W4 + 16 + cg8 * 2); *(float4*)&wb[4] = __ldg(W4 + 16 + cg8 * 2 + 1);
    *(float4*)&wc[0] = __ldg(W4 + 32 + cg8 * 2); *(float4*)&wc[4] = __ldg(W4 + 32 + cg8 * 2 + 1);
    *(float4*)&bv[0] = __ldg((const float4*)bias + cg8 * 2);
    *(float4*)&bv[4] = __ldg((const float4*)bias + cg8 * 2 + 1);
    uint32_t ww[4];
#pragma unroll
    for (int j = 0; j < 4; j++) {
        float e0 = fmaxf(fmaf(x2, wc[2 * j],     fmaf(x1, wb[2 * j],     fmaf(x0, wa[2 * j],     bv[2 * j]))), 0.f);
        float e1 = fmaxf(fmaf(x2, wc[2 * j + 1], fmaf(x1, wb[2 * j + 1], fmaf(x0, wa[2 * j + 1], bv[2 * j + 1]))), 0.f);
        ww[j] = packbf(e0, e1);
    }
    ((uint4*)g_h)[i8] = *(uint4*)ww;
}

// ============================================================================
// Shared epilogue (32x32 warp tiles): bf16 STG + register stats via shfl.
// 8 warps: rg in 0..3 (32 rows each), cg in 0..1 (32 cols each).
// ============================================================================
__device__ __forceinline__ void epilogue(float acc[2][4][4], float* sF,
                                         int r0, int rg, int cg, int g, int tg,
                                         int tid, int bid) {
#pragma unroll
    for (int h = 0; h < 2; h++) {
        __nv_bfloat16* yo = g_y + (size_t)(r0 + rg * 32 + h * 16 + g) * HH + cg * 32 + 2 * tg;
#pragma unroll
        for (int nt = 0; nt < 4; nt++) {
            *(uint32_t*)(yo + nt * 8)          = packbf(acc[h][nt][0], acc[h][nt][1]);
            *(uint32_t*)(yo + 8 * HH + nt * 8) = packbf(acc[h][nt][2], acc[h][nt][3]);
        }
    }
    float cs[8], cq[8];
#pragma unroll
    for (int nt = 0; nt < 4; nt++) {
        cs[2 * nt]     = acc[0][nt][0] + acc[0][nt][2] + acc[1][nt][0] + acc[1][nt][2];
        cs[2 * nt + 1] = acc[0][nt][1] + acc[0][nt][3] + acc[1][nt][1] + acc[1][nt][3];
        cq[2 * nt]     = acc[0][nt][0] * acc[0][nt][0] + acc[0][nt][2] * acc[0][nt][2]
                       + acc[1][nt][0] * acc[1][nt][0] + acc[1][nt][2] * acc[1][nt][2];
        cq[2 * nt + 1] = acc[0][nt][1] * acc[0][nt][1] + acc[0][nt][3] * acc[0][nt][3]
                       + acc[1][nt][1] * acc[1][nt][1] + acc[1][nt][3] * acc[1][nt][3];
    }
#pragma unroll
    for (int off = 4; off <= 16; off <<= 1) {
#pragma unroll
        for (int i = 0; i < 8; i++) {
            cs[i] += __shfl_xor_sync(0xffffffffu, cs[i], off);
            cq[i] += __shfl_xor_sync(0xffffffffu, cq[i], off);
        }
    }
    __syncthreads();
    float* sS = sF;            // [4 rg][64]
    float* sQ = sF + 256;      // [4 rg][64]
    if (g == 0) {
#pragma unroll
        for (int nt = 0; nt < 4; nt++) {
            int col = cg * 32 + nt * 8 + 2 * tg;
            sS[rg * 64 + col]     = cs[2 * nt];
            sS[rg * 64 + col + 1] = cs[2 * nt + 1];
            sQ[rg * 64 + col]     = cq[2 * nt];
            sQ[rg * 64 + col + 1] = cq[2 * nt + 1];
        }
    }
    __syncthreads();
    if (tid < 128) {
        int c = tid & 63;
        const float* base = (tid < 64) ? sS : sQ;
        float v = 0.f;
#pragma unroll
        for (int w4 = 0; w4 < 4; w4++) v += base[w4 * 64 + c];
        g_statsP[(size_t)tid * NBLK1 + bid] = v;
    }
}

// ---------------- GEMM1: y = [h | stencil(h)/4] @ W1, + channel stats --------
__global__ void __launch_bounds__(256, 4) gemm1_k(const float* __restrict__ W) {
    extern __shared__ uint32_t smw[];
    uint32_t* sA = smw;                  // 128 x LDA1W words ([h(32w)|agg(32w)])
    uint32_t* sB = smw + 128 * LDA1W;    // 64  x LDB1W words
    int tid = threadIdx.x;
    int r0 = blockIdx.x << 7;
    int b  = r0 >> 15;
    int n0 = r0 & (NNODE - 1);
    int t  = n0 >> 8;
    int z0 = n0 & 255;
    const __nv_bfloat16* hb = g_h + (size_t)b * NNODE * HH;
    {
        int row = tid >> 1, ch0 = (tid & 1) << 5;
        int z = z0 + row;
        int iC  = ((t << 8) + z) * HH;
        int izm = ((t << 8) + ((z - 1) & 255)) * HH;
        int izp = ((t << 8) + ((z + 1) & 255)) * HH;
        int itm = ((((t - 1) & 127) << 8) + z) * HH;
        int itp = ((((t + 1) & 127) << 8) + z) * HH;
        uint32_t* aw = sA + row * LDA1W + (ch0 >> 1);
#pragma unroll
        for (int i = 0; i < 4; i++) {
            int co = ch0 + i * 8;
            uint4 c = *(const uint4*)(hb + iC + co);
            uint4 p = *(const uint4*)(hb + izm + co);
            uint4 q = *(const uint4*)(hb + izp + co);
            uint4 r = *(const uint4*)(hb + itm + co);
            uint4 s = *(const uint4*)(hb + itp + co);
            *(uint4*)(aw + i * 4) = c;          // center: exact bf16 copy
            uint32_t ag[4];
#pragma unroll
            for (int j = 0; j < 4; j++) {
                float2 pp = upf(((uint32_t*)&p)[j]);
                float2 qq = upf(((uint32_t*)&q)[j]);
                float2 rr = upf(((uint32_t*)&r)[j]);
                float2 ss = upf(((uint32_t*)&s)[j]);
                ag[j] = packbf((pp.x + qq.x + rr.x + ss.x) * 0.25f,
                               (pp.y + qq.y + rr.y + ss.y) * 0.25f);
            }
            *(uint4*)(aw + 32 + i * 4) = *(uint4*)ag;
        }
        // weights: K=128, N=64 -> B[n][kw], kw packs (2kw, 2kw+1)
        int n = tid & 63, kq = tid >> 6;
#pragma unroll
        for (int i = 0; i < 16; i++) {
            int kw = kq * 16 + i;
            float lo = __ldg(W + (2 * kw) * 64 + n);
            float hi = __ldg(W + (2 * kw + 1) * 64 + n);
            sB[n * LDB1W + kw] = packbf(lo, hi);
        }
    }
    __syncthreads();

    int lane = tid & 31, w = tid >> 5;
    int rg = w & 3, cg = w >> 2;
    int g = lane >> 2, tg = lane & 3;
    uint32_t sA32 = (uint32_t)__cvta_generic_to_shared(sA);
    uint32_t aA0 = sA32 + (((rg * 32 + (lane & 15)) * LDA1W) + ((lane >> 4) << 2)) * 4;
    uint32_t aA1 = aA0 + 16 * LDA1W * 4;
    float acc[2][4][4];
#pragma unroll
    for (int h = 0; h < 2; h++)
#pragma unroll
        for (int i = 0; i < 4; i++)
#pragma unroll
            for (int j = 0; j < 4; j++) acc[h][i][j] = 0.f;
    const uint32_t* B0 = sB + (cg * 32 + g) * LDB1W + tg;
#pragma unroll
    for (int ks = 0; ks < 8; ks++) {
        int kb = ks * 8;
        uint32_t a0[4], a1[4];
        ldsm4(a0[0], a0[1], a0[2], a0[3], aA0 + kb * 4);
        ldsm4(a1[0], a1[1], a1[2], a1[3], aA1 + kb * 4);
#pragma unroll
        for (int nt = 0; nt < 4; nt++) {
            uint32_t b0 = B0[nt * 8 * LDB1W + kb];
            uint32_t b1 = B0[nt * 8 * LDB1W + kb + 4];
            mma16(acc[0][nt], a0[0], a0[1], a0[2], a0[3], b0, b1);
            mma16(acc[1][nt], a1[0], a1[1], a1[2], a1[3], b0, b1);
        }
    }
    epilogue(acc, (float*)sA, r0, rg, cg, g, tg, tid, blockIdx.x);
}

// ---------------- GEMM2: y = relu(bn1(y)) @ W2 (in place), + channel stats ---
__global__ void __launch_bounds__(256, 4) gemm2_k(const float* __restrict__ W) {
    extern __shared__ uint32_t smw[];
    uint32_t* sA = smw;                  // 128 x LDA2W
    uint32_t* sB = smw + 128 * LDA2W;    // 64  x LDB2W
    int tid = threadIdx.x;
    int r0 = blockIdx.x << 7;
    {
        int row = tid >> 1, ch0 = (tid & 1) << 5;
        const __nv_bfloat16* yb = g_y + (size_t)(r0 + row) * HH;
        uint32_t* aw = sA + row * LDA2W + (ch0 >> 1);
#pragma unroll
        for (int i = 0; i < 4; i++) {
            int co = ch0 + i * 8;
            uint4 v = *(const uint4*)(yb + co);
            uint32_t ow[4];
#pragma unroll
            for (int j = 0; j < 4; j++) {
                int ch = co + 2 * j;
                float2 f  = upf(((uint32_t*)&v)[j]);
                float2 sc = *(const float2*)(g_ss + ch);
                float2 sh = *(const float2*)(g_ss + 64 + ch);
                ow[j] = packbf(fmaxf(fmaf(f.x, sc.x, sh.x), 0.f),
                               fmaxf(fmaf(f.y, sc.y, sh.y), 0.f));
            }
            *(uint4*)(aw + i * 4) = *(uint4*)ow;
        }
        // weights: K=64, N=64
        int n = tid & 63, kq = tid >> 6;
#pragma unroll
        for (int i = 0; i < 8; i++) {
            int kw = kq * 8 + i;
            float lo = __ldg(W + (2 * kw) * 64 + n);
            float hi = __ldg(W + (2 * kw + 1) * 64 + n);
            sB[n * LDB2W + kw] = packbf(lo, hi);
        }
    }
    __syncthreads();

    int lane = tid & 31, w = tid >> 5;
    int rg = w & 3, cg = w >> 2;
    int g = lane >> 2, tg = lane & 3;
    uint32_t sA32 = (uint32_t)__cvta_generic_to_shared(sA);
    uint32_t aA0 = sA32 + (((rg * 32 + (lane & 15)) * LDA2W) + ((lane >> 4) << 2)) * 4;
    uint32_t aA1 = aA0 + 16 * LDA2W * 4;
    float acc[2][4][4];
#pragma unroll
    for (int h = 0; h < 2; h++)
#pragma unroll
        for (int i = 0; i < 4; i++)
#pragma unroll
            for (int j = 0; j < 4; j++) acc[h][i][j] = 0.f;
    const uint32_t* B0 = sB + (cg * 32 + g) * LDB2W + tg;
#pragma unroll
    for (int ks = 0; ks < 4; ks++) {
        int kb = ks * 8;
        uint32_t a0[4], a1[4];
        ldsm4(a0[0], a0[1], a0[2], a0[3], aA0 + kb * 4);
        ldsm4(a1[0], a1[1], a1[2], a1[3], aA1 + kb * 4);
#pragma unroll
        for (int nt = 0; nt < 4; nt++) {
            uint32_t b0 = B0[nt * 8 * LDB2W + kb];
            uint32_t b1 = B0[nt * 8 * LDB2W + kb + 4];
            mma16(acc[0][nt], a0[0], a0[1], a0[2], a0[3], b0, b1);
            mma16(acc[1][nt], a1[0], a1[1], a1[2], a1[3], b0, b1);
        }
    }
    epilogue(acc, (float*)sA, r0, rg, cg, g, tg, tid, blockIdx.x);
}

// ---------------- stats finalize: scale/shift per channel (fp64) -------------
__global__ void finalize_k(const float* __restrict__ gma, const float* __restrict__ be,
                           int slot) {
    int c = blockIdx.x, tid = threadIdx.x;
    double s = 0.0, s2 = 0.0;
    for (int k = tid; k < NBLK1; k += 256) {
        s  += (double)g_statsP[(size_t)c * NBLK1 + k];
        s2 += (double)g_statsP[(size_t)(64 + c) * NBLK1 + k];
    }
    __shared__ double shs[256], shq[256];
    shs[tid] = s; shq[tid] = s2;
    __syncthreads();
    for (int st = 128; st; st >>= 1) {
        if (tid < st) { shs[tid] += shs[tid + st]; shq[tid] += shq[tid + st]; }
        __syncthreads();
    }
    if (tid == 0) {
        double mean = shs[0] / (double)MTOT;
        double var  = shq[0] / (double)MTOT - mean * mean;
        float sc = (float)((double)__ldg(gma + c) / sqrt(var + 1e-5));
        g_ss[slot * 128 + c]      = sc;
        g_ss[slot * 128 + 64 + c] = __ldg(be + c) - (float)mean * sc;
    }
}

// ---------------- residual: h += relu(y*scale + shift)  (bf16) ---------------
__global__ void resid_k() {
    int base = blockIdx.x << 10;
#pragma unroll
    for (int j = 0; j < 4; j++) {
        int i8 = base + (j << 8) + threadIdx.x;
        int cg8 = i8 & 7;
        uint4 yv = ((const uint4*)g_y)[i8];
        uint4 hv = ((const uint4*)g_h)[i8];
        const float2* scp = (const float2*)(g_ss + 128) + cg8 * 4;
        const float2* shp = (const float2*)(g_ss + 192) + cg8 * 4;
        uint32_t ow[4];
#pragma unroll
        for (int k = 0; k < 4; k++) {
            float2 y2 = upf(((uint32_t*)&yv)[k]);
            float2 h2 = upf(((uint32_t*)&hv)[k]);
            float2 sc = scp[k], sh = shp[k];
            ow[k] = packbf(h2.x + fmaxf(fmaf(y2.x, sc.x, sh.x), 0.f),
                           h2.y + fmaxf(fmaf(y2.y, sc.y, sh.y), 0.f));
        }
        ((uint4*)g_h)[i8] = *(uint4*)ow;
    }
}

// ---------------- pooling partials over nodes (bf16 in, fp32 out) ------------
__global__ void pool_k() {     // grid (32,16), block (32,8)
    int b = blockIdx.y, chunk = blockIdx.x;
    int c2 = threadIdx.x, r = threadIdx.y;
    const __nv_bfloat16* hb = g_h + ((size_t)b * NNODE + (chunk << 10)) * HH;
    float s0 = 0.f, s1 = 0.f;
#pragma unroll 8
    for (int i = 0; i < 128; i++) {
        int off = ((i << 3) + r) * HH + c2 * 2;
        float2 f = upf(*(const uint32_t*)(hb + off));
        s0 += f.x; s1 += f.y;
    }
    __shared__ float sb[8][64];
    sb[r][c2 * 2] = s0; sb[r][c2 * 2 + 1] = s1;
    __syncthreads();
    int tid = r * 32 + c2;
    if (tid < 64) {
        float v = 0.f;
#pragma unroll
        for (int k = 0; k < 8; k++) v += sb[k][tid];
        g_poolP[((b << 5) + chunk) * 64 + tid] = v;
    }
}

// ---------------- head: out = relu(pooled@W1+b1)@W2+b2 (fp32 exact) ----------
__global__ void head_k(const float* __restrict__ W1, const float* __restrict__ b1,
                       const float* __restrict__ W2, const float* __restrict__ b2,
                       float* __restrict__ out) {
    __shared__ float pooled[16 * 64], z1[16 * 64];
    int tid = threadIdx.x;
    for (int i = tid; i < 1024; i += 256) {
        int bb = i >> 6, c = i & 63;
        float s = 0.f;
        const float* pp = g_poolP + (bb << 5) * 64 + c;
#pragma unroll 8
        for (int k = 0; k < 32; k++) s += pp[k * 64];
        pooled[i] = s * (1.0f / NNODE);
    }
    __syncthreads();
    for (int i = tid; i < 1024; i += 256) {
        int bb = i >> 6, j = i & 63;
        float s = __ldg(b1 + j);
        const float* pv = pooled + (bb << 6);
#pragma unroll 8
        for (int c2 = 0; c2 < 64; c2++) s = fmaf(pv[c2], __ldg(W1 + c2 * 64 + j), s);
        z1[i] = fmaxf(s, 0.f);
    }
    __syncthreads();
    for (int i = tid; i < 2048; i += 256) {
        int bb = i >> 7, d = i & 127;
        float s = __ldg(b2 + d);
        const float* zv = z1 + (bb << 6);
#pragma unroll 8
        for (int j = 0; j < 64; j++) s = fmaf(zv[j], __ldg(W2 + j * 128 + d), s);
        out[(bb << 7) + d] = s;
    }
}

// ---------------- launch ----------------
extern "C" void kernel_launch(void* const* d_in, const int* in_sizes, int n_in,
                              void* d_out, int out_size) {
    (void)in_sizes; (void)n_in; (void)out_size;
    const float* x    = (const float*)d_in[0];
    // d_in[1] edge_index: fixed torus stencil, computed analytically
    const float* embW = (const float*)d_in[2];
    const float* embB = (const float*)d_in[3];
    const float* W1   = (const float*)d_in[4];
    // d_in[5] mp_b1: cancels through BatchNorm exactly
    const float* g1   = (const float*)d_in[6];
    const float* be1  = (const float*)d_in[7];
    const float* W2   = (const float*)d_in[8];
    // d_in[9] mp_b2: cancels through BatchNorm exactly
    const float* g2   = (const float*)d_in[10];
    const float* be2  = (const float*)d_in[11];
    const float* hW1  = (const float*)d_in[12];
    const float* hb1  = (const float*)d_in[13];
    const float* hW2  = (const float*)d_in[14];
    const float* hb2  = (const float*)d_in[15];
    float* out = (float*)d_out;

    const int SM1 = (128 * LDA1W + 64 * LDB1W) * 4;   // 52224 B
    const int SM2 = (128 * LDA2W + 64 * LDB2W) * 4;   // 27648 B
    cudaFuncSetAttribute(gemm1_k, cudaFuncAttributeMaxDynamicSharedMemorySize, SM1);
    cudaFuncSetAttribute(gemm2_k, cudaFuncAttributeMaxDynamicSharedMemorySize, SM2);

    embed_k<<<16384, 256>>>(x, embW, embB);
    for (int l = 0; l < 3; l++) {
        gemm1_k<<<NBLK1, 256, SM1>>>(W1 + l * 8192);
        finalize_k<<<64, 256>>>(g1 + l * 64, be1 + l * 64, 0);
        gemm2_k<<<NBLK1, 256, SM2>>>(W2 + l * 4096);
        finalize_k<<<64, 256>>>(g2 + l * 64, be2 + l * 64, 1);
        resid_k<<<4096, 256>>>();
    }
    pool_k<<<dim3(32, 16), dim3(32, 8)>>>();
    head_k<<<1, 256>>>(hW1, hb1, hW2, hb2, out);
}